// round 17
// baseline (speedup 1.0000x reference)
#include <cuda_runtime.h>

// ---------------------------------------------------------------------------
// Compile-time Clebsch-Gordan coefficients (Racah formula), matching numpy ref.
// ---------------------------------------------------------------------------

__host__ __device__ constexpr double cfact(int n) {
    double r = 1.0;
    for (int i = 2; i <= n; ++i) r *= (double)i;
    return r;
}

__host__ __device__ constexpr double csqrt_(double x) {
    if (x <= 0.0) return 0.0;
    double g = x > 1.0 ? x : 1.0;
    for (int i = 0; i < 100; ++i) g = 0.5 * (g + x / g);
    return g;
}

__host__ __device__ constexpr double cg_elem(int l1, int l2, int L, int m1, int m2) {
    const int M = m1 + m2;
    if (M < -L || M > L) return 0.0;
    const double pref0 = csqrt_((2.0 * L + 1.0) * cfact(L + l1 - l2) * cfact(L - l1 + l2) *
                                cfact(l1 + l2 - L) / cfact(l1 + l2 + L + 1));
    const double pref = pref0 * csqrt_(cfact(L + M) * cfact(L - M) * cfact(l1 - m1) *
                                       cfact(l1 + m1) * cfact(l2 - m2) * cfact(l2 + m2));
    double s = 0.0;
    for (int k = 0; k <= l1 + l2 - L; ++k) {
        if (l1 - m1 - k < 0 || l2 + m2 - k < 0 || L - l2 + m1 + k < 0 || L - l1 - m2 + k < 0)
            continue;
        const double d = cfact(k) * cfact(l1 + l2 - L - k) * cfact(l1 - m1 - k) *
                         cfact(l2 + m2 - k) * cfact(L - l2 + m1 + k) * cfact(L - l1 - m2 + k);
        s += ((k & 1) ? -1.0 : 1.0) / d;
    }
    return pref * s;
}

__host__ __device__ constexpr bool cg_nz(double c) { return c > 1e-12 || c < -1e-12; }

__host__ __device__ constexpr bool okL(int l1, int l2, int L, int a, int b) {
    const int off = l1 + l2 - L;
    const int mu = a + b - off;
    return mu >= 0 && mu <= 2 * L && cg_nz(cg_elem(l1, l2, L, a - l1, b - l2));
}

__host__ __device__ constexpr bool pair_any(int l1, int l2, int Lmin, int Lmax,
                                            int p, int q, int m, int n) {
    for (int L = Lmin; L <= Lmax; ++L)
        if (okL(l1, l2, L, m, n) && okL(l1, l2, L, p, q)) return true;
    return false;
}

__host__ __device__ constexpr bool col_any_p(int l1, int l2, int Lmin, int Lmax, int p, int q) {
    for (int L = Lmin; L <= Lmax; ++L)
        if (okL(l1, l2, L, p, q)) return true;
    return false;
}

__host__ __device__ constexpr bool col_any_q_par(int l1, int l2, int Lmin, int Lmax,
                                                 int q, bool sym, int PAR) {
    const int pmax = sym ? q : 2 * l1;
    for (int p = 0; p <= pmax; ++p)
        if (((p + q) & 1) == PAR && col_any_p(l1, l2, Lmin, Lmax, p, q)) return true;
    return false;
}

__host__ __device__ constexpr bool row_any(int l1, int l2, int Lmin, int Lmax,
                                           int p, int q, int m, int nlo) {
    for (int nn = nlo; nn <= 2 * l2; ++nn)
        if (pair_any(l1, l2, Lmin, Lmax, p, q, m, nn)) return true;
    return false;
}

// ---------------------------------------------------------------------------
// Column-major padded smem matrix: X[r][c] stored at base[c*PAD + r].
// Logical columns are contiguous -> LDS.128 loads (strides chosen so the
// float4-granule lane stride is odd => bank-conflict-free across the warp).
// ---------------------------------------------------------------------------

template <int d_, int PAD_>
struct PadMat {
    static constexpr int d = d_;
    static constexpr int pad = PAD_;
    const float* p;
    // logical index I = r*d + c
    template <int I> __device__ __forceinline__ float at() const {
        return p[(I % d) * PAD_ + (I / d)];
    }
};

// Vectorized load of logical column `col` (d contiguous floats + pad).
template <int d, int PAD, int col>
__device__ __forceinline__ void load_colv(const float* base, float (&dst)[d]) {
    const float4* v = reinterpret_cast<const float4*>(base + col * PAD);
    float4 a = v[0];
    dst[0] = a.x;
    if constexpr (d > 1) dst[1] = a.y;
    if constexpr (d > 2) dst[2] = a.z;
    if constexpr (d > 3) dst[3] = a.w;
    if constexpr (d > 4) {
        float4 b = v[1];
        dst[4] = b.x;
        if constexpr (d > 5) dst[5] = b.y;
        if constexpr (d > 6) dst[6] = b.z;
    }
}

// ---------------------------------------------------------------------------
// Accumulator group (only owned-parity entries are written; rest DCE'd)
// ---------------------------------------------------------------------------

struct EAcc {
    float e0[1];
    float e1[9];
    float e2[25];
    float e3[49];
};

template <int L> __device__ __forceinline__ auto& getE(EAcc& a) {
    if constexpr (L == 0) return a.e0;
    else if constexpr (L == 1) return a.e1;
    else if constexpr (L == 2) return a.e2;
    else return a.e3;
}

template <int N>
__device__ __forceinline__ void zeroa(float (&e)[N]) {
#pragma unroll
    for (int i = 0; i < N; ++i) e[i] = 0.f;
}

// ---------------------------------------------------------------------------
// CG scatter: one product feeds an FFMA-imm per valid L in [Lmin,Lmax].
// ---------------------------------------------------------------------------

template <int l1, int l2, int p, int q, int m, int n, int W, int L, int Lmax>
__device__ __forceinline__ void l_scatter(float prod, EAcc& acc) {
    if constexpr (L <= Lmax) {
        if constexpr (okL(l1, l2, L, m, n) && okL(l1, l2, L, p, q)) {
            constexpr int off = l1 + l2 - L, DL = 2 * L + 1;
            constexpr int mu = m + n - off, nu = p + q - off;
            constexpr float w = (float)((double)W * cg_elem(l1, l2, L, m - l1, n - l2) *
                                        cg_elem(l1, l2, L, p - l1, q - l2));
            getE<L>(acc)[mu * DL + nu] = __fmaf_rn(w, prod, getE<L>(acc)[mu * DL + nu]);
        }
        l_scatter<l1, l2, p, q, m, n, W, L + 1, Lmax>(prod, acc);
    }
}

template <int l1, int l2, int p, int q, int m, int BW, bool SYMIN, int Lmin, int Lmax, int n>
__device__ __forceinline__ void n_loop(float am, const float (&bcol)[2 * l2 + 1], EAcc& acc) {
    if constexpr (n < 2 * l2 + 1) {
        if constexpr (!(SYMIN && m > n) && pair_any(l1, l2, Lmin, Lmax, p, q, m, n)) {
            float prod = am * bcol[n];
            l_scatter<l1, l2, p, q, m, n, BW*((SYMIN && m < n) ? 2 : 1), Lmin, Lmax>(prod, acc);
        }
        n_loop<l1, l2, p, q, m, BW, SYMIN, Lmin, Lmax, n + 1>(am, bcol, acc);
    }
}

// m loop over a register-cached acol (vector-loaded; no per-m LDS)
template <int l1, int l2, int p, int q, int BW, int Lmin, int Lmax, int m = 0>
__device__ __forceinline__ void m_loop_a(const float (&acol)[2 * l1 + 1],
                                         const float (&bcol)[2 * l2 + 1], EAcc& acc) {
    constexpr int d1 = 2 * l1 + 1;
    if constexpr (m < d1) {
        if constexpr (row_any(l1, l2, Lmin, Lmax, p, q, m, 0)) {
            n_loop<l1, l2, p, q, m, BW, false, Lmin, Lmax, 0>(acol[m], bcol, acc);
        }
        m_loop_a<l1, l2, p, q, BW, Lmin, Lmax, m + 1>(acol, bcol, acc);
    }
}

// diagonal column of a symmetric self term (p == q): both operands from bcol
template <int l, int q, int Lmin, int Lmax, int m = 0>
__device__ __forceinline__ void m_loop_diag(const float (&bcol)[2 * l + 1], EAcc& acc) {
    if constexpr (m < 2 * l + 1) {
        if constexpr (row_any(l, l, Lmin, Lmax, q, q, m, m)) {
            n_loop<l, l, q, q, m, 1, true, Lmin, Lmax, m>(bcol[m], bcol, acc);
        }
        m_loop_diag<l, q, Lmin, Lmax, m + 1>(bcol, acc);
    }
}

// ----- cross term (A != B), weight BW, column-parity PAR -----

template <int l1, int l2, int BW, int Lmin, int Lmax, int PAR, class MA, int q, int p = 0>
__device__ __forceinline__ void p_multi(const MA& A, const float (&bcol)[2 * l2 + 1], EAcc& acc) {
    constexpr int d1 = 2 * l1 + 1;
    if constexpr (p < d1) {
        if constexpr (((p + q) & 1) == PAR && col_any_p(l1, l2, Lmin, Lmax, p, q)) {
            float acol[d1];
            load_colv<d1, MA::pad, p>(A.p, acol);
            m_loop_a<l1, l2, p, q, BW, Lmin, Lmax>(acol, bcol, acc);
        }
        p_multi<l1, l2, BW, Lmin, Lmax, PAR, MA, q, p + 1>(A, bcol, acc);
    }
}

template <int l1, int l2, int BW, int Lmin, int Lmax, int PAR, class MA, class MB, int q = 0>
__device__ __forceinline__ void term_multi(const MA& A, const MB& Bm, EAcc& acc) {
    constexpr int d2 = 2 * l2 + 1;
    if constexpr (q < d2) {
        if constexpr (col_any_q_par(l1, l2, Lmin, Lmax, q, false, PAR)) {
            float bcol[d2];
            load_colv<d2, MB::pad, q>(Bm.p, bcol);
            p_multi<l1, l2, BW, Lmin, Lmax, PAR, MA, q>(A, bcol, acc);
        }
        term_multi<l1, l2, BW, Lmin, Lmax, PAR, MA, MB, q + 1>(A, Bm, acc);
    }
}

// ----- symmetric self term A(x)A: p<q weight 2 full inner; p==q inner m<=n -----

template <int l, int Lmin, int Lmax, int PAR, class MA, int q, int p = 0>
__device__ __forceinline__ void p_sym_multi(const MA& A, const float (&bcol)[2 * l + 1],
                                            EAcc& acc) {
    constexpr int d = 2 * l + 1;
    if constexpr (p <= q) {
        if constexpr (((p + q) & 1) == PAR && col_any_p(l, l, Lmin, Lmax, p, q)) {
            if constexpr (p < q) {
                float acol[d];
                load_colv<d, MA::pad, p>(A.p, acol);
                m_loop_a<l, l, p, q, 2, Lmin, Lmax>(acol, bcol, acc);
            } else {
                m_loop_diag<l, q, Lmin, Lmax>(bcol, acc);
            }
        }
        p_sym_multi<l, Lmin, Lmax, PAR, MA, q, p + 1>(A, bcol, acc);
    }
}

template <int l, int Lmin, int Lmax, int PAR, class MA, int q = 0>
__device__ __forceinline__ void term_sym_multi(const MA& A, EAcc& acc) {
    constexpr int d = 2 * l + 1;
    if constexpr (q < d) {
        if constexpr (col_any_q_par(l, l, Lmin, Lmax, q, true, PAR)) {
            float bcol[d];
            load_colv<d, MA::pad, q>(A.p, bcol);
            p_sym_multi<l, Lmin, Lmax, PAR, MA, q>(A, bcol, acc);
        }
        term_sym_multi<l, Lmin, Lmax, PAR, MA, q + 1>(A, acc);
    }
}

// ----- (0,l) term, parity-filtered, vectorized per owned column -----

template <int d, int NUP, class M, int c = 0>
__device__ __forceinline__ void axpy_cols(float t, const M& X, float (&e)[d * d]) {
    if constexpr (c < d) {
        if constexpr ((c & 1) == NUP) {
            float col[d];
            load_colv<d, M::pad, c>(X.p, col);
#pragma unroll
            for (int r = 0; r < d; ++r) e[r * d + c] = __fmaf_rn(t, col[r], e[r * d + c]);
        }
        axpy_cols<d, NUP, M, c + 1>(t, X, e);
    }
}

// ----- L=0 contractions over the owned column class -----

template <int L, int NUP, class MB, int ij = 0>
__device__ __forceinline__ void invar_mat_par(const float (&A)[(2 * L + 1) * (2 * L + 1)],
                                              const MB& Bm, float& s) {
    constexpr int D = 2 * L + 1;
    if constexpr (ij < D * D) {
        if constexpr (((ij % D) & 1) == NUP) {
            constexpr int i = ij / D, j = ij % D;
            constexpr float w = (((i + j) & 1) ? -1.0f : 1.0f) / (float)D;
            s = __fmaf_rn(w, A[ij] * Bm.template at<(D - 1 - i) * D + (D - 1 - j)>(), s);
        }
        invar_mat_par<L, NUP, MB, ij + 1>(A, Bm, s);
    }
}

template <int L, int NUP, int ij = 0>
__device__ __forceinline__ void invar_self_par(const float (&A)[(2 * L + 1) * (2 * L + 1)],
                                               float& s) {
    constexpr int D = 2 * L + 1, DD = D * D;
    if constexpr (ij <= (DD - 1) / 2) {
        if constexpr (((ij % D) & 1) == NUP) {
            constexpr int i = ij / D, j = ij % D;
            constexpr float base = (ij == DD - 1 - ij) ? 1.0f : 2.0f;
            constexpr float w = (((i + j) & 1) ? -base : base) / (float)D;
            s = __fmaf_rn(w, A[ij] * A[DD - 1 - ij], s);
        }
        invar_self_par<L, NUP, ij + 1>(A, s);
    }
}

// ---------------------------------------------------------------------------
// Pass bodies (round-12 structure: phase A = even terms all L, phase B = odd).
// ---------------------------------------------------------------------------

using M1t = PadMat<3, 4>;
using M2t = PadMat<5, 8>;
using M3t = PadMat<7, 8>;

template <int PAR>
__device__ __forceinline__ void passA(const M1t& S1, const M2t& S2, const M3t& S3,
                                      float X0, float& out2, float& out3, float* o01) {
    EAcc a;
    zeroa(a.e0); zeroa(a.e1); zeroa(a.e2); zeroa(a.e3);
    if constexpr (PAR == 0) a.e0[0] = X0 * X0;   // (0,0) column parity 0
    term_sym_multi<1, 0, 2, PAR>(S1, a);         // (1,1) -> L=0,1,2
    term_sym_multi<2, 0, 3, PAR>(S2, a);         // (2,2) -> L=0..3
    term_sym_multi<3, 0, 3, PAR>(S3, a);         // (3,3) -> L=0..3
    term_multi<1, 3, 2, 2, 3, PAR>(S1, S3, a);   // (1,3)x2 -> L=2,3
    axpy_cols<5, PAR>(X0 + X0, S2, a.e2);        // (0,2)x2 -> L=2
    if constexpr (PAR == 0) {
        out2 = __fmaf_rn(a.e0[0], X0, out2);
        out3 = __fmaf_rn(a.e0[0], a.e0[0], out3);
        if (o01) { o01[0] = X0; o01[1] = a.e0[0]; }
    }
    invar_self_par<1, PAR ^ 1>(a.e1, out3);      // (1,-)
    invar_mat_par<2, PAR>(a.e2, S2, out2);       // (2,+) x X2
    invar_self_par<2, PAR>(a.e2, out3);
    invar_self_par<3, PAR ^ 1>(a.e3, out3);      // (3,-)
}

template <int PAR>
__device__ __forceinline__ void passB(const M1t& S1, const M2t& S2, const M3t& S3,
                                      float X0, float& out2, float& out3) {
    EAcc a;
    zeroa(a.e1); zeroa(a.e2); zeroa(a.e3);
    axpy_cols<3, PAR>(X0 + X0, S1, a.e1);        // (0,1)x2 -> L=1
    term_multi<1, 2, 2, 1, 3, PAR>(S1, S2, a);   // (1,2)x2 -> L=1..3
    term_multi<2, 3, 2, 1, 3, PAR>(S2, S3, a);   // (2,3)x2 -> L=1..3
    axpy_cols<7, PAR>(X0 + X0, S3, a.e3);        // (0,3)x2 -> L=3
    invar_mat_par<1, PAR>(a.e1, S1, out2);       // (1,+) x X1
    invar_self_par<1, PAR>(a.e1, out3);
    invar_self_par<2, PAR ^ 1>(a.e2, out3);      // (2,-)
    invar_mat_par<3, PAR>(a.e3, S3, out2);       // (3,+) x X3
    invar_self_par<3, PAR>(a.e3, out3);
}

// ---------------------------------------------------------------------------
// Kernel: TWO threads per batch element (column-parity split), 2 merged passes.
// Column-major padded smem: element strides 12/44/60 floats (odd /4 => CF
// LDS.128). 256-thread CTAs, 84-reg cap (3 CTAs/SM, 24 warps/SM).
// ---------------------------------------------------------------------------

constexpr int O0 = 0;
constexpr int O1 = 128;                   // + 128*12 = 1536
constexpr int O2 = O1 + 128 * 12;         // 1664; + 128*44 = 5632
constexpr int O3 = O2 + 128 * 44;         // 7296; + 128*60 = 7680
constexpr int SM_DATA = O3 + 128 * 60;    // 14976 floats
constexpr int SM_FLOATS = SM_DATA + 256;  // + comb
constexpr int SMEM_BYTES = SM_FLOATS * 4; // 60928 B (> 48KB static -> dynamic)

__global__ void __launch_bounds__(256, 3)
wigner_kernel(const float* __restrict__ gx0, const float* __restrict__ gx1,
              const float* __restrict__ gx2, const float* __restrict__ gx3,
              float* __restrict__ out, int n) {
    extern __shared__ float sm[];
    float* comb = sm + SM_DATA;
    const int tid = threadIdx.x;
    const int elem = tid & 127;
    const int half = tid >> 7;
    const int base = blockIdx.x * 128;

    // Transposing stage into column-major padded layout.
    if (base + 128 <= n) {  // full CTA
        if (tid < 128) sm[O0 + tid] = gx0[base + tid];
        for (int idx = tid; idx < 1152; idx += 256) {
            int e = idx / 9, w = idx % 9;
            sm[O1 + e * 12 + (w % 3) * 4 + (w / 3)] = gx1[(size_t)base * 9 + idx];
        }
        for (int idx = tid; idx < 3200; idx += 256) {
            int e = idx / 25, w = idx % 25;
            sm[O2 + e * 44 + (w % 5) * 8 + (w / 5)] = gx2[(size_t)base * 25 + idx];
        }
        for (int idx = tid; idx < 6272; idx += 256) {
            int e = idx / 49, w = idx % 49;
            sm[O3 + e * 60 + (w % 7) * 8 + (w / 7)] = gx3[(size_t)base * 49 + idx];
        }
    } else {  // tail CTA: bounds + zero fill
        const int c = n - base;
        if (tid < 128) sm[O0 + tid] = (tid < c) ? gx0[base + tid] : 0.f;
        for (int idx = tid; idx < 1152; idx += 256) {
            int e = idx / 9, w = idx % 9;
            float v = (idx < c * 9) ? gx1[(size_t)base * 9 + idx] : 0.f;
            sm[O1 + e * 12 + (w % 3) * 4 + (w / 3)] = v;
        }
        for (int idx = tid; idx < 3200; idx += 256) {
            int e = idx / 25, w = idx % 25;
            float v = (idx < c * 25) ? gx2[(size_t)base * 25 + idx] : 0.f;
            sm[O2 + e * 44 + (w % 5) * 8 + (w / 5)] = v;
        }
        for (int idx = tid; idx < 6272; idx += 256) {
            int e = idx / 49, w = idx % 49;
            float v = (idx < c * 49) ? gx3[(size_t)base * 49 + idx] : 0.f;
            sm[O3 + e * 60 + (w % 7) * 8 + (w / 7)] = v;
        }
    }
    __syncthreads();

    const int b = base + elem;
    const bool valid = (b < n);

    const M1t S1{sm + O1 + elem * 12};
    const M2t S2{sm + O2 + elem * 44};
    const M3t S3{sm + O3 + elem * 60};
    const float X0 = sm[O0 + elem];

    float out2 = 0.f, out3 = 0.f;
    float* o01 = (valid && half == 0) ? (out + (size_t)b * 4) : nullptr;

    if (half == 0) passA<0>(S1, S2, S3, X0, out2, out3, o01);
    else           passA<1>(S1, S2, S3, X0, out2, out3, o01);
    // no barrier needed: smem is read-only between passes
    if (half == 0) passB<0>(S1, S2, S3, X0, out2, out3);
    else           passB<1>(S1, S2, S3, X0, out2, out3);

    // combine the two parity halves
    if (half == 1) {
        comb[elem] = out2;
        comb[128 + elem] = out3;
    }
    __syncthreads();
    if (half == 0 && valid) {
        out[b * 4 + 2] = out2 + comb[elem];
        out[b * 4 + 3] = out3 + comb[128 + elem];
    }
}

// ---------------------------------------------------------------------------
// Harness entry point
// ---------------------------------------------------------------------------

extern "C" void kernel_launch(void* const* d_in, const int* in_sizes, int n_in,
                              void* d_out, int out_size) {
    const float* x0 = (const float*)d_in[0];
    const float* x1 = (const float*)d_in[1];
    const float* x2 = (const float*)d_in[2];
    const float* x3 = (const float*)d_in[3];
    float* out = (float*)d_out;

    static bool attr_set = false;
    if (!attr_set) {
        cudaFuncSetAttribute(wigner_kernel,
                             cudaFuncAttributeMaxDynamicSharedMemorySize, SMEM_BYTES);
        cudaFuncSetAttribute(wigner_kernel,
                             cudaFuncAttributePreferredSharedMemoryCarveout, 100);
        attr_set = true;
    }

    const int n = in_sizes[0];  // B
    const int grid = (n + 127) / 128;
    wigner_kernel<<<grid, 256, SMEM_BYTES>>>(x0, x1, x2, x3, out, n);
}